// round 1
// baseline (speedup 1.0000x reference)
#include <cuda_runtime.h>

#define NN 150000      // nodes
#define NE 450000      // edges
#define NG 5000        // graphs
#define HH 256         // hidden
#define H4 64          // HH/4
#define JKD 1536       // (L+1)*H
#define NL 5

// ---------------- scratch (device globals; no allocation allowed) ----------
__device__ float g_h    [NN * HH];
__device__ float g_hprev[NN * HH];
__device__ float g_agg  [NN * HH];
__device__ float g_t    [NN * HH];
__device__ float g_z2   [NN * HH];
__device__ float g_jk   [NN * JKD];
__device__ float g_vn   [NG * HH];
__device__ float g_vnagg[NG * HH];

static __device__ __forceinline__ float4 f4zero() { return make_float4(0.f,0.f,0.f,0.f); }

// ---------------- embed: h = atom_emb[x]; jk[:,0:256]=h; vn init; vnagg=0 ---
__global__ void k_embed(const int* __restrict__ x,
                        const float* __restrict__ atom_emb,
                        const float* __restrict__ vn0) {
    int i = blockIdx.x * blockDim.x + threadIdx.x;   // float4 index over NN*H4
    if (i < NG * H4) {
        ((float4*)g_vnagg)[i] = f4zero();
        ((float4*)g_vn)[i] = ((const float4*)vn0)[i & (H4 - 1)];
    }
    if (i >= NN * H4) return;
    int n = i >> 6, c4 = i & 63;
    float4 v = ((const float4*)atom_emb)[x[n] * H4 + c4];
    ((float4*)g_h)[i] = v;
    ((float4*)g_jk)[(size_t)n * (JKD / 4) + c4] = v;
}

// ---------------- layer pre: h += vn[batch]; hprev = h; agg = 0 -------------
__global__ void k_vnadd(const int* __restrict__ batch) {
    int i = blockIdx.x * blockDim.x + threadIdx.x;
    if (i >= NN * H4) return;
    int n = i >> 6, c4 = i & 63;
    float4 hv = ((float4*)g_h)[i];
    float4 vv = ((const float4*)g_vn)[batch[n] * H4 + c4];
    hv.x += vv.x; hv.y += vv.y; hv.z += vv.z; hv.w += vv.w;
    ((float4*)g_h)[i]     = hv;
    ((float4*)g_hprev)[i] = hv;
    ((float4*)g_agg)[i]   = f4zero();
}

// ---------------- edge messages: agg[dst] += relu(h[src] + bond[ea]) --------
__global__ void k_msg(const int* __restrict__ ei, const int* __restrict__ ea,
                      const float* __restrict__ bond) {
    int e = blockIdx.x * 8 + threadIdx.y;
    if (e >= NE) return;
    int src = ei[e], dst = ei[NE + e], bt = ea[e];
    const float4* hs = (const float4*)g_h + (size_t)src * H4;
    const float4* be = (const float4*)bond + bt * H4;
    float* ad = g_agg + (size_t)dst * HH;
    for (int i = threadIdx.x; i < H4; i += 32) {
        float4 a = hs[i], b = be[i];
        float m0 = fmaxf(a.x + b.x, 0.f);
        float m1 = fmaxf(a.y + b.y, 0.f);
        float m2 = fmaxf(a.z + b.z, 0.f);
        float m3 = fmaxf(a.w + b.w, 0.f);
        atomicAdd(ad + 4*i + 0, m0);
        atomicAdd(ad + 4*i + 1, m1);
        atomicAdd(ad + 4*i + 2, m2);
        atomicAdd(ad + 4*i + 3, m3);
    }
}

// ---------------- SGEMM: C[M,256] = op(A)[M,K] @ B[K,256] + bias ------------
// FUSEA: A-element = (1+eps[layer])*A + A2 (fuses the GINE combine).
// 128x128 tile, BK=8, 256 threads, 8x8 per thread.
template <bool FUSEA, bool DO_RELU>
__global__ void __launch_bounds__(256)
k_gemm(const float* __restrict__ A, const float* __restrict__ A2,
       const float* __restrict__ eps, int layer,
       const float* __restrict__ B, const float* __restrict__ bias,
       float* __restrict__ C, int M, int K) {
    __shared__ float As[8][128];
    __shared__ float Bs[8][128];
    const int tid  = threadIdx.x;
    const int brow = blockIdx.y * 128;
    const int bcol = blockIdx.x * 128;

    float alpha = 1.f;
    if (FUSEA) alpha = 1.f + __ldg(&eps[layer]);

    const int ar = tid >> 1;          // 0..127
    const int ac = (tid & 1) * 4;     // 0 / 4
    const int br = tid >> 5;          // 0..7
    const int bc = (tid & 31) * 4;    // 0..124
    const int ty = tid >> 4;          // 0..15
    const int tx = tid & 15;          // 0..15

    const int  arow   = brow + ar;
    const bool avalid = arow < M;
    const float* Ap  = A  + (size_t)arow * K + ac;
    const float* A2p = FUSEA ? (A2 + (size_t)arow * K + ac) : A;

    float acc[8][8];
    #pragma unroll
    for (int i = 0; i < 8; i++)
        #pragma unroll
        for (int j = 0; j < 8; j++) acc[i][j] = 0.f;

    for (int kt = 0; kt < K; kt += 8) {
        float4 av = f4zero();
        if (avalid) {
            av = *(const float4*)(Ap + kt);
            if (FUSEA) {
                float4 a2 = *(const float4*)(A2p + kt);
                av.x = alpha * av.x + a2.x;
                av.y = alpha * av.y + a2.y;
                av.z = alpha * av.z + a2.z;
                av.w = alpha * av.w + a2.w;
            }
        }
        As[ac + 0][ar] = av.x;
        As[ac + 1][ar] = av.y;
        As[ac + 2][ar] = av.z;
        As[ac + 3][ar] = av.w;
        float4 bv = *(const float4*)(B + (size_t)(kt + br) * 256 + bcol + bc);
        *(float4*)&Bs[br][bc] = bv;
        __syncthreads();
        #pragma unroll
        for (int k = 0; k < 8; k++) {
            float4 a0 = *(const float4*)&As[k][ty * 8];
            float4 a1 = *(const float4*)&As[k][ty * 8 + 4];
            float4 b0 = *(const float4*)&Bs[k][tx * 8];
            float4 b1 = *(const float4*)&Bs[k][tx * 8 + 4];
            float aa[8] = {a0.x,a0.y,a0.z,a0.w,a1.x,a1.y,a1.z,a1.w};
            float bb[8] = {b0.x,b0.y,b0.z,b0.w,b1.x,b1.y,b1.z,b1.w};
            #pragma unroll
            for (int i = 0; i < 8; i++)
                #pragma unroll
                for (int j = 0; j < 8; j++)
                    acc[i][j] = fmaf(aa[i], bb[j], acc[i][j]);
        }
        __syncthreads();
    }

    float bs[8];
    #pragma unroll
    for (int j = 0; j < 8; j++) bs[j] = bias[bcol + tx * 8 + j];

    #pragma unroll
    for (int i = 0; i < 8; i++) {
        int row = brow + ty * 8 + i;
        if (row < M) {
            float* cp = C + (size_t)row * 256 + bcol + tx * 8;
            float o[8];
            #pragma unroll
            for (int j = 0; j < 8; j++) {
                float v = acc[i][j] + bs[j];
                o[j] = DO_RELU ? fmaxf(v, 0.f) : v;
            }
            *(float4*)(cp + 0) = make_float4(o[0], o[1], o[2], o[3]);
            *(float4*)(cp + 4) = make_float4(o[4], o[5], o[6], o[7]);
        }
    }
}

// ------- LN + relu + residual; write h & jk block; vn segment-sum -----------
__global__ void __launch_bounds__(256)
k_lnres(const int* __restrict__ batch, const float* __restrict__ lng,
        const float* __restrict__ lnb, int layer) {
    int w = threadIdx.x >> 5, lane = threadIdx.x & 31;
    int r = blockIdx.x * 8 + w;
    if (r >= NN) return;
    const float* z = g_z2 + (size_t)r * HH;
    float v[8], s = 0.f, ss = 0.f;
    #pragma unroll
    for (int j = 0; j < 8; j++) {
        v[j] = z[lane + 32 * j];
        s += v[j]; ss += v[j] * v[j];
    }
    #pragma unroll
    for (int o = 16; o; o >>= 1) {
        s  += __shfl_xor_sync(0xffffffffu, s,  o);
        ss += __shfl_xor_sync(0xffffffffu, ss, o);
    }
    float mean = s * (1.f / HH);
    float var  = ss * (1.f / HH) - mean * mean;
    float rstd = rsqrtf(var + 1e-5f);

    float*       hp  = g_h     + (size_t)r * HH;
    const float* pv  = g_hprev + (size_t)r * HH;
    float*       jkp = g_jk    + (size_t)r * JKD + (layer + 1) * HH;
    float*       va  = g_vnagg + (size_t)batch[r] * HH;
    #pragma unroll
    for (int j = 0; j < 8; j++) {
        int c = lane + 32 * j;
        float y = (v[j] - mean) * rstd * lng[c] + lnb[c];
        y = fmaxf(y, 0.f);
        float o = y + pv[c];
        hp[c]  = o;
        jkp[c] = o;
        atomicAdd(va + c, o);
    }
}

// ------- virtual node: vn = relu(LN((vnagg+vn) @ W + b)); reset vnagg -------
__global__ void __launch_bounds__(256)
k_vn(const float* __restrict__ w, const float* __restrict__ bias,
     const float* __restrict__ lng, const float* __restrict__ lnb) {
    int g = blockIdx.x, t = threadIdx.x;
    __shared__ float s[HH];
    __shared__ float red[2][8];
    float sv = g_vnagg[(size_t)g * HH + t] + g_vn[(size_t)g * HH + t];
    s[t] = sv;
    g_vnagg[(size_t)g * HH + t] = 0.f;   // reset for next layer
    __syncthreads();
    float acc = bias[t];
    #pragma unroll 8
    for (int k = 0; k < HH; k++) acc = fmaf(s[k], w[k * HH + t], acc);
    // block LN over the 256 outputs
    float sm = acc, sq = acc * acc;
    int lane = t & 31, wid = t >> 5;
    #pragma unroll
    for (int o = 16; o; o >>= 1) {
        sm += __shfl_xor_sync(0xffffffffu, sm, o);
        sq += __shfl_xor_sync(0xffffffffu, sq, o);
    }
    if (lane == 0) { red[0][wid] = sm; red[1][wid] = sq; }
    __syncthreads();
    float tot = 0.f, tot2 = 0.f;
    #pragma unroll
    for (int i = 0; i < 8; i++) { tot += red[0][i]; tot2 += red[1][i]; }
    float mean = tot * (1.f / HH);
    float var  = tot2 * (1.f / HH) - mean * mean;
    float rstd = rsqrtf(var + 1e-5f);
    float y = (acc - mean) * rstd * lng[t] + lnb[t];
    g_vn[(size_t)g * HH + t] = fmaxf(y, 0.f);
}

// ------- head stage 2: out[N,28] = t[N,256] @ w2[256,28] + b2 ---------------
__global__ void k_head2(const float* __restrict__ w2, const float* __restrict__ b2,
                        float* __restrict__ out) {
    int c = threadIdx.x;
    int r = blockIdx.x * blockDim.y + threadIdx.y;
    if (r >= NN || c >= 28) return;
    const float* tr = g_t + (size_t)r * HH;
    float acc = 0.f;
    #pragma unroll 8
    for (int k = 0; k < HH; k++) acc = fmaf(tr[k], w2[k * 28 + c], acc);
    out[(size_t)r * 28 + c] = acc + b2[c];
}

// ---------------------------------------------------------------------------
extern "C" void kernel_launch(void* const* d_in, const int* in_sizes, int n_in,
                              void* d_out, int out_size) {
    const int*   x     = (const int*)  d_in[0];
    const int*   ei    = (const int*)  d_in[1];
    const int*   ea    = (const int*)  d_in[2];
    const int*   batch = (const int*)  d_in[3];
    const float* aemb  = (const float*)d_in[4];
    const float* bemb  = (const float*)d_in[5];
    const float* vn0   = (const float*)d_in[6];
    const float* w1    = (const float*)d_in[7];
    const float* b1    = (const float*)d_in[8];
    const float* w2    = (const float*)d_in[9];
    const float* b2    = (const float*)d_in[10];
    const float* eps   = (const float*)d_in[11];
    const float* lng   = (const float*)d_in[12];
    const float* lnb   = (const float*)d_in[13];
    const float* vnw   = (const float*)d_in[14];
    const float* vnb   = (const float*)d_in[15];
    const float* vlg   = (const float*)d_in[16];
    const float* vlb   = (const float*)d_in[17];
    const float* hw1   = (const float*)d_in[18];
    const float* hb1   = (const float*)d_in[19];
    const float* hw2   = (const float*)d_in[20];
    const float* hb2   = (const float*)d_in[21];
    float* out = (float*)d_out;

    float *p_h, *p_agg, *p_t, *p_z2, *p_jk;
    cudaGetSymbolAddress((void**)&p_h,   g_h);
    cudaGetSymbolAddress((void**)&p_agg, g_agg);
    cudaGetSymbolAddress((void**)&p_t,   g_t);
    cudaGetSymbolAddress((void**)&p_z2,  g_z2);
    cudaGetSymbolAddress((void**)&p_jk,  g_jk);

    const int nb_nh = (NN * H4 + 255) / 256;
    dim3 ggrid(2, (NN + 127) / 128);

    k_embed<<<nb_nh, 256>>>(x, aemb, vn0);

    for (int l = 0; l < NL; l++) {
        k_vnadd<<<nb_nh, 256>>>(batch);
        k_msg<<<(NE + 7) / 8, dim3(32, 8)>>>(ei, ea, bemb);
        // t = relu(((1+eps)*h + agg) @ w1 + b1)
        k_gemm<true, true><<<ggrid, 256>>>(p_h, p_agg, eps, l,
                                           w1 + (size_t)l * HH * HH,
                                           b1 + l * HH, p_t, NN, HH);
        // z2 = t @ w2 + b2
        k_gemm<false, false><<<ggrid, 256>>>(p_t, nullptr, eps, l,
                                             w2 + (size_t)l * HH * HH,
                                             b2 + l * HH, p_z2, NN, HH);
        k_lnres<<<(NN + 7) / 8, 256>>>(batch, lng + l * HH, lnb + l * HH, l);
        k_vn<<<NG, 256>>>(vnw + (size_t)l * HH * HH, vnb + l * HH,
                          vlg + l * HH, vlb + l * HH);
    }

    // head: t = relu(jk @ hw1 + hb1);  out = t @ hw2 + hb2
    k_gemm<false, true><<<ggrid, 256>>>(p_jk, nullptr, eps, 0,
                                        hw1, hb1, p_t, NN, JKD);
    k_head2<<<(NN + 7) / 8, dim3(32, 8)>>>(hw2, hb2, out);
}

// round 2
// speedup vs baseline: 1.1098x; 1.1098x over previous
#include <cuda_runtime.h>
#include <cstdint>

#define NN  150000     // nodes
#define NNP 150016     // padded to multiple of 128 (1172*128)
#define NE  450000     // edges
#define NG  5000       // graphs
#define HH  256        // hidden
#define H4  64         // HH/4
#define JKD 1536       // (L+1)*H
#define NL  5

// ---------------- scratch (device globals; no allocation allowed) ----------
__device__ float g_h    [NNP * HH];
__device__ float g_hprev[NNP * HH];
__device__ float g_agg  [NNP * HH];
__device__ float g_t    [NNP * HH];
__device__ float g_z2   [NNP * HH];
__device__ float g_jk   [NNP * JKD];
__device__ float g_vn   [NG * HH];
__device__ float g_vnagg[NG * HH];

static __device__ __forceinline__ float4 f4zero() { return make_float4(0.f,0.f,0.f,0.f); }

static __device__ __forceinline__ uint32_t tf32cvt(float f) {
    uint32_t u;
    asm("cvt.rna.tf32.f32 %0, %1;" : "=r"(u) : "f"(f));
    return u;
}
static __device__ __forceinline__ void tf32split(float f, uint32_t& hi, uint32_t& lo) {
    hi = tf32cvt(f);
    lo = tf32cvt(f - __uint_as_float(hi));
}
static __device__ __forceinline__ void mma8(float c[4], const uint32_t a[4],
                                            uint32_t b0, uint32_t b1) {
    asm volatile(
        "mma.sync.aligned.m16n8k8.row.col.f32.tf32.tf32.f32 "
        "{%0,%1,%2,%3},{%4,%5,%6,%7},{%8,%9},{%0,%1,%2,%3};"
        : "+f"(c[0]), "+f"(c[1]), "+f"(c[2]), "+f"(c[3])
        : "r"(a[0]), "r"(a[1]), "r"(a[2]), "r"(a[3]), "r"(b0), "r"(b1));
}

// ---------------- embed: h = atom_emb[x]; jk[:,0:256]=h; vn init; vnagg=0 ---
__global__ void k_embed(const int* __restrict__ x,
                        const float* __restrict__ atom_emb,
                        const float* __restrict__ vn0) {
    int i = blockIdx.x * blockDim.x + threadIdx.x;
    if (i < NG * H4) {
        ((float4*)g_vnagg)[i] = f4zero();
        ((float4*)g_vn)[i] = ((const float4*)vn0)[i & (H4 - 1)];
    }
    if (i >= NN * H4) return;
    int n = i >> 6, c4 = i & 63;
    float4 v = ((const float4*)atom_emb)[x[n] * H4 + c4];
    ((float4*)g_h)[i] = v;
    ((float4*)g_jk)[(size_t)n * (JKD / 4) + c4] = v;
}

// ---------------- layer pre: h += vn[batch]; hprev = h; agg = 0 -------------
__global__ void k_vnadd(const int* __restrict__ batch) {
    int i = blockIdx.x * blockDim.x + threadIdx.x;
    if (i >= NN * H4) return;
    int n = i >> 6, c4 = i & 63;
    float4 hv = ((float4*)g_h)[i];
    float4 vv = ((const float4*)g_vn)[batch[n] * H4 + c4];
    hv.x += vv.x; hv.y += vv.y; hv.z += vv.z; hv.w += vv.w;
    ((float4*)g_h)[i]     = hv;
    ((float4*)g_hprev)[i] = hv;
    ((float4*)g_agg)[i]   = f4zero();
}

// ---------------- edge messages: agg[dst] += relu(h[src] + bond[ea]) --------
__global__ void k_msg(const int* __restrict__ ei, const int* __restrict__ ea,
                      const float* __restrict__ bond) {
    int e = blockIdx.x * 8 + threadIdx.y;
    if (e >= NE) return;
    int src = ei[e], dst = ei[NE + e], bt = ea[e];
    const float4* hs = (const float4*)g_h + (size_t)src * H4;
    const float4* be = (const float4*)bond + bt * H4;
    float* ad = g_agg + (size_t)dst * HH;
    for (int i = threadIdx.x; i < H4; i += 32) {
        float4 a = hs[i], b = be[i];
        float m0 = fmaxf(a.x + b.x, 0.f);
        float m1 = fmaxf(a.y + b.y, 0.f);
        float m2 = fmaxf(a.z + b.z, 0.f);
        float m3 = fmaxf(a.w + b.w, 0.f);
        atomicAdd(ad + 4*i + 0, m0);
        atomicAdd(ad + 4*i + 1, m1);
        atomicAdd(ad + 4*i + 2, m2);
        atomicAdd(ad + 4*i + 3, m3);
    }
}

// ---------------- TF32 tensor-core GEMM: C[M,256] = op(A)[M,K] @ B[K,256] ---
// 3xTF32 split for fp32-class accuracy. FUSEA: A := (1+eps[layer])*A + A2.
// BM=128, BN=128, BK=16, 256 threads (8 warps, 4x2), warp tile 32x64.
// M must be a multiple of 128 (scratch is padded); no row bounds checks.
template <bool FUSEA, bool DO_RELU>
__global__ void __launch_bounds__(256)
k_gemm_tc(const float* __restrict__ A, const float* __restrict__ A2,
          const float* __restrict__ eps, int layer,
          const float* __restrict__ B, const float* __restrict__ bias,
          float* __restrict__ C, int K) {
    __shared__ float As[2][128][20];   // stride 20 ≡ 4 (mod 8): conflict-free frag lds
    __shared__ float Bs[2][16][136];   // stride 136 ≡ 8 (mod 32): conflict-free frag lds

    const int tid  = threadIdx.x;
    const int brow = blockIdx.y * 128;
    const int bcol = blockIdx.x * 128;

    float alpha = 1.f;
    if (FUSEA) alpha = 1.f + __ldg(&eps[layer]);

    const int warp = tid >> 5, lane = tid & 31;
    const int wm = warp & 3, wn = warp >> 2;      // 4 x 2 warp grid
    const int g  = lane >> 2, t = lane & 3;

    // global->reg load mapping
    const int arow0 = tid >> 2;        // 0..63 (+64 on pass 1)
    const int ac4   = (tid & 3) * 4;   // 0,4,8,12
    const int bk0   = tid >> 5;        // 0..7 (+8 on pass 1)
    const int bc4   = (tid & 31) * 4;  // 0..124

    float4 aReg[2], bReg[2];
    const int ntiles = K >> 4;

    auto ldgTile = [&](int kt) {
        #pragma unroll
        for (int p = 0; p < 2; p++) {
            int r = arow0 + p * 64;
            const float* ap = A + (size_t)(brow + r) * K + kt * 16 + ac4;
            float4 v = *(const float4*)ap;
            if (FUSEA) {
                float4 v2 = *(const float4*)(A2 + (size_t)(brow + r) * K + kt * 16 + ac4);
                v.x = fmaf(alpha, v.x, v2.x);
                v.y = fmaf(alpha, v.y, v2.y);
                v.z = fmaf(alpha, v.z, v2.z);
                v.w = fmaf(alpha, v.w, v2.w);
            }
            aReg[p] = v;
        }
        #pragma unroll
        for (int p = 0; p < 2; p++) {
            int k = bk0 + p * 8;
            bReg[p] = *(const float4*)(B + (size_t)(kt * 16 + k) * 256 + bcol + bc4);
        }
    };
    auto stsTile = [&](int buf) {
        #pragma unroll
        for (int p = 0; p < 2; p++)
            *(float4*)&As[buf][arow0 + p * 64][ac4] = aReg[p];
        #pragma unroll
        for (int p = 0; p < 2; p++)
            *(float4*)&Bs[buf][bk0 + p * 8][bc4] = bReg[p];
    };

    float c[2][8][4];
    #pragma unroll
    for (int mi = 0; mi < 2; mi++)
        #pragma unroll
        for (int ni = 0; ni < 8; ni++)
            #pragma unroll
            for (int j = 0; j < 4; j++) c[mi][ni][j] = 0.f;

    ldgTile(0);
    stsTile(0);
    __syncthreads();
    int cur = 0;

    for (int kt = 0; kt < ntiles; kt++) {
        if (kt + 1 < ntiles) ldgTile(kt + 1);
        #pragma unroll
        for (int kk = 0; kk < 16; kk += 8) {
            uint32_t ah[2][4], al[2][4];
            #pragma unroll
            for (int mi = 0; mi < 2; mi++) {
                int r = wm * 32 + mi * 16 + g;
                float f0 = As[cur][r    ][kk + t];
                float f1 = As[cur][r + 8][kk + t];
                float f2 = As[cur][r    ][kk + t + 4];
                float f3 = As[cur][r + 8][kk + t + 4];
                tf32split(f0, ah[mi][0], al[mi][0]);
                tf32split(f1, ah[mi][1], al[mi][1]);
                tf32split(f2, ah[mi][2], al[mi][2]);
                tf32split(f3, ah[mi][3], al[mi][3]);
            }
            #pragma unroll
            for (int ni = 0; ni < 8; ni++) {
                int n = wn * 64 + ni * 8 + g;
                float fb0 = Bs[cur][kk + t    ][n];
                float fb1 = Bs[cur][kk + t + 4][n];
                uint32_t bh0, bl0, bh1, bl1;
                tf32split(fb0, bh0, bl0);
                tf32split(fb1, bh1, bl1);
                #pragma unroll
                for (int mi = 0; mi < 2; mi++) {
                    mma8(c[mi][ni], al[mi], bh0, bh1);   // lo*hi
                    mma8(c[mi][ni], ah[mi], bl0, bl1);   // hi*lo
                    mma8(c[mi][ni], ah[mi], bh0, bh1);   // hi*hi
                }
            }
        }
        if (kt + 1 < ntiles) {
            stsTile(1 - cur);
            __syncthreads();
            cur ^= 1;
        }
    }

    // epilogue
    #pragma unroll
    for (int mi = 0; mi < 2; mi++) {
        int r0 = brow + wm * 32 + mi * 16 + g;
        #pragma unroll
        for (int ni = 0; ni < 8; ni++) {
            int col = bcol + wn * 64 + ni * 8 + t * 2;
            float b0 = __ldg(&bias[col]), b1 = __ldg(&bias[col + 1]);
            float v0 = c[mi][ni][0] + b0, v1 = c[mi][ni][1] + b1;
            float v2 = c[mi][ni][2] + b0, v3 = c[mi][ni][3] + b1;
            if (DO_RELU) {
                v0 = fmaxf(v0, 0.f); v1 = fmaxf(v1, 0.f);
                v2 = fmaxf(v2, 0.f); v3 = fmaxf(v3, 0.f);
            }
            *(float2*)(C + (size_t)r0 * 256 + col)       = make_float2(v0, v1);
            *(float2*)(C + (size_t)(r0 + 8) * 256 + col) = make_float2(v2, v3);
        }
    }
}

// ------- LN + relu + residual; write h & jk block; vn segment-sum -----------
__global__ void __launch_bounds__(256)
k_lnres(const int* __restrict__ batch, const float* __restrict__ lng,
        const float* __restrict__ lnb, int layer) {
    int w = threadIdx.x >> 5, lane = threadIdx.x & 31;
    int r = blockIdx.x * 8 + w;
    if (r >= NN) return;
    const float* z = g_z2 + (size_t)r * HH;
    float v[8], s = 0.f, ss = 0.f;
    #pragma unroll
    for (int j = 0; j < 8; j++) {
        v[j] = z[lane + 32 * j];
        s += v[j]; ss += v[j] * v[j];
    }
    #pragma unroll
    for (int o = 16; o; o >>= 1) {
        s  += __shfl_xor_sync(0xffffffffu, s,  o);
        ss += __shfl_xor_sync(0xffffffffu, ss, o);
    }
    float mean = s * (1.f / HH);
    float var  = ss * (1.f / HH) - mean * mean;
    float rstd = rsqrtf(var + 1e-5f);

    float*       hp  = g_h     + (size_t)r * HH;
    const float* pv  = g_hprev + (size_t)r * HH;
    float*       jkp = g_jk    + (size_t)r * JKD + (layer + 1) * HH;
    float*       va  = g_vnagg + (size_t)batch[r] * HH;
    #pragma unroll
    for (int j = 0; j < 8; j++) {
        int c = lane + 32 * j;
        float y = (v[j] - mean) * rstd * lng[c] + lnb[c];
        y = fmaxf(y, 0.f);
        float o = y + pv[c];
        hp[c]  = o;
        jkp[c] = o;
        atomicAdd(va + c, o);
    }
}

// ------- virtual node: vn = relu(LN((vnagg+vn) @ W + b)); reset vnagg -------
__global__ void __launch_bounds__(256)
k_vn(const float* __restrict__ w, const float* __restrict__ bias,
     const float* __restrict__ lng, const float* __restrict__ lnb) {
    int g = blockIdx.x, t = threadIdx.x;
    __shared__ float s[HH];
    __shared__ float red[2][8];
    float sv = g_vnagg[(size_t)g * HH + t] + g_vn[(size_t)g * HH + t];
    s[t] = sv;
    g_vnagg[(size_t)g * HH + t] = 0.f;   // reset for next layer
    __syncthreads();
    float acc = bias[t];
    #pragma unroll 8
    for (int k = 0; k < HH; k++) acc = fmaf(s[k], w[k * HH + t], acc);
    float sm = acc, sq = acc * acc;
    int lane = t & 31, wid = t >> 5;
    #pragma unroll
    for (int o = 16; o; o >>= 1) {
        sm += __shfl_xor_sync(0xffffffffu, sm, o);
        sq += __shfl_xor_sync(0xffffffffu, sq, o);
    }
    if (lane == 0) { red[0][wid] = sm; red[1][wid] = sq; }
    __syncthreads();
    float tot = 0.f, tot2 = 0.f;
    #pragma unroll
    for (int i = 0; i < 8; i++) { tot += red[0][i]; tot2 += red[1][i]; }
    float mean = tot * (1.f / HH);
    float var  = tot2 * (1.f / HH) - mean * mean;
    float rstd = rsqrtf(var + 1e-5f);
    float y = (acc - mean) * rstd * lng[t] + lnb[t];
    g_vn[(size_t)g * HH + t] = fmaxf(y, 0.f);
}

// ------- head stage 2: out[N,28] = t[N,256] @ w2[256,28] + b2 ---------------
__global__ void k_head2(const float* __restrict__ w2, const float* __restrict__ b2,
                        float* __restrict__ out) {
    int c = threadIdx.x;
    int r = blockIdx.x * blockDim.y + threadIdx.y;
    if (r >= NN || c >= 28) return;
    const float* tr = g_t + (size_t)r * HH;
    float acc = 0.f;
    #pragma unroll 8
    for (int k = 0; k < HH; k++) acc = fmaf(tr[k], w2[k * 28 + c], acc);
    out[(size_t)r * 28 + c] = acc + b2[c];
}

// ---------------------------------------------------------------------------
extern "C" void kernel_launch(void* const* d_in, const int* in_sizes, int n_in,
                              void* d_out, int out_size) {
    const int*   x     = (const int*)  d_in[0];
    const int*   ei    = (const int*)  d_in[1];
    const int*   ea    = (const int*)  d_in[2];
    const int*   batch = (const int*)  d_in[3];
    const float* aemb  = (const float*)d_in[4];
    const float* bemb  = (const float*)d_in[5];
    const float* vn0   = (const float*)d_in[6];
    const float* w1    = (const float*)d_in[7];
    const float* b1    = (const float*)d_in[8];
    const float* w2    = (const float*)d_in[9];
    const float* b2    = (const float*)d_in[10];
    const float* eps   = (const float*)d_in[11];
    const float* lng   = (const float*)d_in[12];
    const float* lnb   = (const float*)d_in[13];
    const float* vnw   = (const float*)d_in[14];
    const float* vnb   = (const float*)d_in[15];
    const float* vlg   = (const float*)d_in[16];
    const float* vlb   = (const float*)d_in[17];
    const float* hw1   = (const float*)d_in[18];
    const float* hb1   = (const float*)d_in[19];
    const float* hw2   = (const float*)d_in[20];
    const float* hb2   = (const float*)d_in[21];
    float* out = (float*)d_out;

    float *p_h, *p_agg, *p_t, *p_z2, *p_jk;
    cudaGetSymbolAddress((void**)&p_h,   g_h);
    cudaGetSymbolAddress((void**)&p_agg, g_agg);
    cudaGetSymbolAddress((void**)&p_t,   g_t);
    cudaGetSymbolAddress((void**)&p_z2,  g_z2);
    cudaGetSymbolAddress((void**)&p_jk,  g_jk);

    const int nb_nh = (NN * H4 + 255) / 256;
    dim3 ggrid(2, NNP / 128);   // 2 x 1172, M padded: no bounds checks

    k_embed<<<nb_nh, 256>>>(x, aemb, vn0);

    for (int l = 0; l < NL; l++) {
        k_vnadd<<<nb_nh, 256>>>(batch);
        k_msg<<<(NE + 7) / 8, dim3(32, 8)>>>(ei, ea, bemb);
        // t = relu(((1+eps)*h + agg) @ w1 + b1)
        k_gemm_tc<true, true><<<ggrid, 256>>>(p_h, p_agg, eps, l,
                                              w1 + (size_t)l * HH * HH,
                                              b1 + l * HH, p_t, HH);
        // z2 = t @ w2 + b2
        k_gemm_tc<false, false><<<ggrid, 256>>>(p_t, nullptr, eps, l,
                                                w2 + (size_t)l * HH * HH,
                                                b2 + l * HH, p_z2, HH);
        k_lnres<<<(NN + 7) / 8, 256>>>(batch, lng + l * HH, lnb + l * HH, l);
        k_vn<<<NG, 256>>>(vnw + (size_t)l * HH * HH, vnb + l * HH,
                          vlg + l * HH, vlb + l * HH);
    }

    // head: t = relu(jk @ hw1 + hb1);  out = t @ hw2 + hb2
    k_gemm_tc<false, true><<<ggrid, 256>>>(p_jk, nullptr, eps, 0,
                                           hw1, hb1, p_t, JKD);
    k_head2<<<(NN + 7) / 8, dim3(32, 8)>>>(hw2, hb2, out);
}

// round 4
// speedup vs baseline: 1.8283x; 1.6474x over previous
#include <cuda_runtime.h>
#include <cuda_bf16.h>
#include <cstdint>

#define NN  150000     // nodes
#define NNP 150016     // padded to 1172*128
#define NE  450000     // edges
#define NG  5000       // graphs
#define HH  256        // hidden
#define H4  64         // HH/4
#define JKD 1536       // (L+1)*H
#define NL  5

// ---------------- scratch (device globals; zero-initialized) ---------------
__device__ float g_h    [NNP * HH];
__device__ float g_hprev[NNP * HH];
__device__ float g_agg  [NNP * HH];
__device__ float g_t    [NNP * HH];
__device__ float g_z2   [NNP * HH];
__device__ float g_jk   [NNP * JKD];
__device__ float g_vn   [NG * HH];
__device__ float g_vnagg[NG * HH];
// pre-transposed + bf16-split weights: layout [N=256 rows, K cols]
__device__ __nv_bfloat16 g_w1t_hi[NL * HH * HH];
__device__ __nv_bfloat16 g_w1t_lo[NL * HH * HH];
__device__ __nv_bfloat16 g_w2t_hi[NL * HH * HH];
__device__ __nv_bfloat16 g_w2t_lo[NL * HH * HH];
__device__ __nv_bfloat16 g_hw1t_hi[HH * JKD];
__device__ __nv_bfloat16 g_hw1t_lo[HH * JKD];

static __device__ __forceinline__ float4 f4zero() { return make_float4(0.f,0.f,0.f,0.f); }

static __device__ __forceinline__ uint32_t smem_u32(const void* p) {
    uint32_t a;
    asm("{ .reg .u64 t; cvta.to.shared.u64 t, %1; cvt.u32.u64 %0, t; }" : "=r"(a) : "l"(p));
    return a;
}
static __device__ __forceinline__ uint32_t pack_bf(float lo, float hi) {
    uint32_t d;
    asm("cvt.rn.bf16x2.f32 %0, %1, %2;" : "=r"(d) : "f"(hi), "f"(lo));
    return d;
}
static __device__ __forceinline__ void redv4(float* p, float a, float b, float c, float d) {
    asm volatile("red.global.add.v4.f32 [%0], {%1,%2,%3,%4};"
                 :: "l"(p), "f"(a), "f"(b), "f"(c), "f"(d) : "memory");
}
static __device__ __forceinline__ void ldmx4(uint32_t r[4], uint32_t addr) {
    asm volatile("ldmatrix.sync.aligned.m8n8.x4.shared.b16 {%0,%1,%2,%3}, [%4];"
                 : "=r"(r[0]), "=r"(r[1]), "=r"(r[2]), "=r"(r[3]) : "r"(addr));
}
static __device__ __forceinline__ void mma_bf(float c[4], const uint32_t a[4],
                                              uint32_t b0, uint32_t b1) {
    asm volatile("mma.sync.aligned.m16n8k16.row.col.f32.bf16.bf16.f32 "
                 "{%0,%1,%2,%3},{%4,%5,%6,%7},{%8,%9},{%0,%1,%2,%3};"
                 : "+f"(c[0]), "+f"(c[1]), "+f"(c[2]), "+f"(c[3])
                 : "r"(a[0]), "r"(a[1]), "r"(a[2]), "r"(a[3]), "r"(b0), "r"(b1));
}
static __device__ __forceinline__ void cpasync16(uint32_t dst, const void* src) {
    asm volatile("cp.async.cg.shared.global [%0], [%1], 16;" :: "r"(dst), "l"(src));
}

// ---------------- weight prep: W[K,N] -> WT_hi/lo[N,K] bf16 split -----------
__global__ void k_prep(const float* __restrict__ src, __nv_bfloat16* __restrict__ dhi,
                       __nv_bfloat16* __restrict__ dlo, int K, int N, int nmat) {
    int e = blockIdx.x * blockDim.x + threadIdx.x;
    if (e >= nmat * K * N) return;
    int m = e / (K * N), rem = e % (K * N);
    int n = rem / K, k = rem % K;
    float v = src[(size_t)m * K * N + (size_t)k * N + n];
    __nv_bfloat16 h = __float2bfloat16(v);
    __nv_bfloat16 l = __float2bfloat16(v - __bfloat162float(h));
    size_t o = (size_t)m * K * N + (size_t)n * K + k;
    dhi[o] = h; dlo[o] = l;
}

// ---------------- embed ----------------------------------------------------
__global__ void k_embed(const int* __restrict__ x,
                        const float* __restrict__ atom_emb,
                        const float* __restrict__ vn0) {
    int i = blockIdx.x * blockDim.x + threadIdx.x;
    if (i < NG * H4) {
        ((float4*)g_vnagg)[i] = f4zero();
        ((float4*)g_vn)[i] = ((const float4*)vn0)[i & (H4 - 1)];
    }
    if (i >= NN * H4) return;
    int n = i >> 6, c4 = i & 63;
    float4 v = ((const float4*)atom_emb)[x[n] * H4 + c4];
    ((float4*)g_h)[i] = v;
    ((float4*)g_jk)[(size_t)n * (JKD / 4) + c4] = v;
}

// ---------------- layer pre: h += vn[batch]; hprev = h; agg = 0 -------------
__global__ void k_vnadd(const int* __restrict__ batch) {
    int i = blockIdx.x * blockDim.x + threadIdx.x;
    if (i >= NN * H4) return;
    int n = i >> 6, c4 = i & 63;
    float4 hv = ((float4*)g_h)[i];
    float4 vv = ((const float4*)g_vn)[batch[n] * H4 + c4];
    hv.x += vv.x; hv.y += vv.y; hv.z += vv.z; hv.w += vv.w;
    ((float4*)g_h)[i]     = hv;
    ((float4*)g_hprev)[i] = hv;
    ((float4*)g_agg)[i]   = f4zero();
}

// ---------------- edge messages: agg[dst] += relu(h[src] + bond[ea]) --------
__global__ void k_msg(const int* __restrict__ ei, const int* __restrict__ ea,
                      const float* __restrict__ bond) {
    int e = blockIdx.x * 8 + threadIdx.y;
    if (e >= NE) return;
    int src = ei[e], dst = ei[NE + e], bt = ea[e];
    const float4* hs = (const float4*)g_h + (size_t)src * H4;
    const float4* be = (const float4*)bond + bt * H4;
    float* ad = g_agg + (size_t)dst * HH;
    #pragma unroll
    for (int p = 0; p < 2; p++) {
        int i = threadIdx.x + p * 32;
        float4 a = hs[i], b = be[i];
        redv4(ad + 4 * i, fmaxf(a.x + b.x, 0.f), fmaxf(a.y + b.y, 0.f),
                          fmaxf(a.z + b.z, 0.f), fmaxf(a.w + b.w, 0.f));
    }
}

// ======= bf16-split mma.sync GEMM: C[M,256] = op(A)[M,K] @ WT^T + bias ======
// WT stored [256, K] bf16 hi/lo. 3 HMMA (hh, hl, lh) per k16.
// BM=128, BN=128, BK=32. 256 threads, 8 warps (4x2), warp tile 32x64.
// smem row stride 40 bf16 (80B) -> conflict-free ldmatrix.
#define ROWB   80
#define TILE_B (128 * ROWB)       // 10240 B
#define STG_B  (4 * TILE_B)       // Ah | Al | Bh | Bl
#define SMEM_TOT (2 * STG_B)      // 81920 B

template <bool FUSEA, bool DO_RELU>
__global__ void __launch_bounds__(256, 2)
k_gemm_bf(const float* __restrict__ A, const float* __restrict__ A2,
          const float* __restrict__ eps, int layer,
          const __nv_bfloat16* __restrict__ Bh, const __nv_bfloat16* __restrict__ Bl,
          const float* __restrict__ bias, float* __restrict__ C, int K) {
    extern __shared__ __align__(128) char smem[];
    const int tid = threadIdx.x, warp = tid >> 5, lane = tid & 31;
    const int brow = blockIdx.y * 128, bcol = blockIdx.x * 128;
    const int wm = warp & 3, wn = warp >> 2;
    const int nch = K >> 5;

    float alpha = 1.f;
    if (FUSEA) alpha = 1.f + __ldg(&eps[layer]);

    // A load mapping: row = tid/2 (0..127), half = tid&1 -> 16 fp32
    const int ar = tid >> 1, ahf = tid & 1;
    const float* Ap  = A + (size_t)(brow + ar) * K + ahf * 16;
    const float* A2p = FUSEA ? (A2 + (size_t)(brow + ar) * K + ahf * 16) : nullptr;
    // B cp.async mapping: arr = tid/128 (0=hi,1=lo), row = tid&127
    const int bro = tid & 127;
    const __nv_bfloat16* Bp = ((tid >> 7) ? Bl : Bh) + (size_t)(bcol + bro) * K;

    const uint32_t sb = smem_u32(smem);

    auto issue = [&](int c, int s) {
        char* st = smem + s * STG_B;
        // B: 64B via 4 cp.async
        uint32_t bdst = sb + s * STG_B + (2 + (tid >> 7)) * TILE_B + bro * ROWB;
        const char* bsrc = (const char*)(Bp + c * 32);
        #pragma unroll
        for (int j = 0; j < 4; j++) cpasync16(bdst + j * 16, bsrc + j * 16);
        // A: ldg fp32, fuse, split, sts
        const float* ap = Ap + c * 32;
        float f[16];
        #pragma unroll
        for (int j = 0; j < 4; j++) *(float4*)(f + 4 * j) = *(const float4*)(ap + 4 * j);
        if (FUSEA) {
            const float* a2p = A2p + c * 32;
            #pragma unroll
            for (int j = 0; j < 4; j++) {
                float4 u = *(const float4*)(a2p + 4 * j);
                f[4*j+0] = fmaf(alpha, f[4*j+0], u.x);
                f[4*j+1] = fmaf(alpha, f[4*j+1], u.y);
                f[4*j+2] = fmaf(alpha, f[4*j+2], u.z);
                f[4*j+3] = fmaf(alpha, f[4*j+3], u.w);
            }
        }
        uint32_t hi[8], lo[8];
        #pragma unroll
        for (int q = 0; q < 8; q++) {
            float f0 = f[2*q], f1 = f[2*q+1];
            __nv_bfloat16 h0 = __float2bfloat16(f0), h1 = __float2bfloat16(f1);
            hi[q] = ((uint32_t)__bfloat16_as_ushort(h1) << 16) | __bfloat16_as_ushort(h0);
            lo[q] = pack_bf(f0 - __bfloat162float(h0), f1 - __bfloat162float(h1));
        }
        char* arow = st + ar * ROWB + ahf * 32;
        *(uint4*)(arow)               = make_uint4(hi[0], hi[1], hi[2], hi[3]);
        *(uint4*)(arow + 16)          = make_uint4(hi[4], hi[5], hi[6], hi[7]);
        *(uint4*)(arow + TILE_B)      = make_uint4(lo[0], lo[1], lo[2], lo[3]);
        *(uint4*)(arow + TILE_B + 16) = make_uint4(lo[4], lo[5], lo[6], lo[7]);
        asm volatile("cp.async.commit_group;" ::: "memory");
    };

    float acc[2][8][4];
    #pragma unroll
    for (int mi = 0; mi < 2; mi++)
        #pragma unroll
        for (int ni = 0; ni < 8; ni++)
            #pragma unroll
            for (int j = 0; j < 4; j++) acc[mi][ni][j] = 0.f;

    // fragment addresses (per-stage offsets added in loop)
    const uint32_t a_addr = sb + (uint32_t)(wm * 32 + (lane & 15)) * ROWB + (lane >> 4) * 16;
    const int bn = wn * 64 + (lane & 7) + ((lane >> 4) << 3);
    const uint32_t b_addr = sb + 2 * TILE_B + (uint32_t)bn * ROWB + ((lane >> 3) & 1) * 16;

    issue(0, 0);
    for (int c = 0; c < nch; c++) {
        const int s = c & 1;
        if (c + 1 < nch) {
            issue(c + 1, 1 - s);
            asm volatile("cp.async.wait_group 1;" ::: "memory");
        } else {
            asm volatile("cp.async.wait_group 0;" ::: "memory");
        }
        __syncthreads();
        const uint32_t so = s * STG_B;
        #pragma unroll
        for (int k16 = 0; k16 < 2; k16++) {
            uint32_t ah[2][4], al[2][4];
            #pragma unroll
            for (int mi = 0; mi < 2; mi++) {
                uint32_t aa = a_addr + so + mi * (16 * ROWB) + k16 * 32;
                ldmx4(ah[mi], aa);
                ldmx4(al[mi], aa + TILE_B);
            }
            #pragma unroll
            for (int np = 0; np < 4; np++) {
                uint32_t ba = b_addr + so + np * (16 * ROWB) + k16 * 32;
                uint32_t bh[4], bl[4];
                ldmx4(bh, ba);
                ldmx4(bl, ba + TILE_B);
                #pragma unroll
                for (int g = 0; g < 2; g++) {
                    #pragma unroll
                    for (int mi = 0; mi < 2; mi++) {
                        float* cc = acc[mi][np * 2 + g];
                        mma_bf(cc, ah[mi], bh[2*g], bh[2*g+1]);
                        mma_bf(cc, ah[mi], bl[2*g], bl[2*g+1]);
                        mma_bf(cc, al[mi], bh[2*g], bh[2*g+1]);
                    }
                }
            }
        }
        __syncthreads();
    }

    // epilogue
    #pragma unroll
    for (int mi = 0; mi < 2; mi++) {
        int r0 = brow + wm * 32 + mi * 16 + (lane >> 2);
        #pragma unroll
        for (int ni = 0; ni < 8; ni++) {
            int col = bcol + wn * 64 + ni * 8 + (lane & 3) * 2;
            float b0 = __ldg(&bias[col]), b1 = __ldg(&bias[col + 1]);
            float v0 = acc[mi][ni][0] + b0, v1 = acc[mi][ni][1] + b1;
            float v2 = acc[mi][ni][2] + b0, v3 = acc[mi][ni][3] + b1;
            if (DO_RELU) {
                v0 = fmaxf(v0, 0.f); v1 = fmaxf(v1, 0.f);
                v2 = fmaxf(v2, 0.f); v3 = fmaxf(v3, 0.f);
            }
            *(float2*)(C + (size_t)r0 * 256 + col)       = make_float2(v0, v1);
            *(float2*)(C + (size_t)(r0 + 8) * 256 + col) = make_float2(v2, v3);
        }
    }
}

// ------- LN + relu + residual; write h & jk; vn segment-sum (red.v4) --------
__global__ void __launch_bounds__(256)
k_lnres(const int* __restrict__ batch, const float* __restrict__ lng,
        const float* __restrict__ lnb, int layer) {
    int w = threadIdx.x >> 5, lane = threadIdx.x & 31;
    int r = blockIdx.x * 8 + w;
    if (r >= NN) return;
    const float4* z4 = (const float4*)(g_z2 + (size_t)r * HH);
    float4 a = z4[lane * 2], b = z4[lane * 2 + 1];
    float s  = a.x + a.y + a.z + a.w + b.x + b.y + b.z + b.w;
    float ss = a.x*a.x + a.y*a.y + a.z*a.z + a.w*a.w
             + b.x*b.x + b.y*b.y + b.z*b.z + b.w*b.w;
    #pragma unroll
    for (int o = 16; o; o >>= 1) {
        s  += __shfl_xor_sync(0xffffffffu, s,  o);
        ss += __shfl_xor_sync(0xffffffffu, ss, o);
    }
    float mean = s * (1.f / HH);
    float var  = ss * (1.f / HH) - mean * mean;
    float rstd = rsqrtf(var + 1e-5f);

    float4 g0 = ((const float4*)lng)[lane * 2], g1 = ((const float4*)lng)[lane * 2 + 1];
    float4 b0 = ((const float4*)lnb)[lane * 2], b1 = ((const float4*)lnb)[lane * 2 + 1];
    const float4* pv = (const float4*)(g_hprev + (size_t)r * HH);
    float4 p0 = pv[lane * 2], p1 = pv[lane * 2 + 1];

    float4 o0, o1;
    o0.x = fmaxf((a.x - mean) * rstd * g0.x + b0.x, 0.f) + p0.x;
    o0.y = fmaxf((a.y - mean) * rstd * g0.y + b0.y, 0.f) + p0.y;
    o0.z = fmaxf((a.z - mean) * rstd * g0.z + b0.z, 0.f) + p0.z;
    o0.w = fmaxf((a.w - mean) * rstd * g0.w + b0.w, 0.f) + p0.w;
    o1.x = fmaxf((b.x - mean) * rstd * g1.x + b1.x, 0.f) + p1.x;
    o1.y = fmaxf((b.y - mean) * rstd * g1.y + b1.y, 0.f) + p1.y;
    o1.z = fmaxf((b.z - mean) * rstd * g1.z + b1.z, 0.f) + p1.z;
    o1.w = fmaxf((b.w - mean) * rstd * g1.w + b1.w, 0.f) + p1.w;

    ((float4*)(g_h + (size_t)r * HH))[lane * 2]     = o0;
    ((float4*)(g_h + (size_t)r * HH))[lane * 2 + 1] = o1;
    float* jkp = g_jk + (size_t)r * JKD + (layer + 1) * HH;
    ((float4*)jkp)[lane * 2]     = o0;
    ((float4*)jkp)[lane * 2 + 1] = o1;
    float* va = g_vnagg + (size_t)batch[r] * HH + lane * 8;
    redv4(va,     o0.x, o0.y, o0.z, o0.w);
    redv4(va + 4, o1.x, o1.y, o1.z, o1.w);
}

// ------- virtual node: vn = relu(LN((vnagg+vn) @ W + b)); reset vnagg -------
__global__ void __launch_bounds__(256)
k_vn(const float* __restrict__ w, const float* __restrict__ bias,
     const float* __restrict__ lng, const float* __restrict__ lnb) {
    int g = blockIdx.x, t = threadIdx.x;
    __shared__ float s[HH];
    __shared__ float red[2][8];
    float sv = g_vnagg[(size_t)g * HH + t] + g_vn[(size_t)g * HH + t];
    s[t] = sv;
    g_vnagg[(size_t)g * HH + t] = 0.f;
    __syncthreads();
    float acc = bias[t];
    #pragma unroll 8
    for (int k = 0; k < HH; k++) acc = fmaf(s[k], w[k * HH + t], acc);
    float sm = acc, sq = acc * acc;
    int lane = t & 31, wid = t >> 5;
    #pragma unroll
    for (int o = 16; o; o >>= 1) {
        sm += __shfl_xor_sync(0xffffffffu, sm, o);
        sq += __shfl_xor_sync(0xffffffffu, sq, o);
    }
    if (lane == 0) { red[0][wid] = sm; red[1][wid] = sq; }
    __syncthreads();
    float tot = 0.f, tot2 = 0.f;
    #pragma unroll
    for (int i = 0; i < 8; i++) { tot += red[0][i]; tot2 += red[1][i]; }
    float mean = tot * (1.f / HH);
    float var  = tot2 * (1.f / HH) - mean * mean;
    float rstd = rsqrtf(var + 1e-5f);
    float y = (acc - mean) * rstd * lng[t] + lnb[t];
    g_vn[(size_t)g * HH + t] = fmaxf(y, 0.f);
}

// ------- head stage 2: out[N,28] = t[N,256] @ w2[256,28] + b2 ---------------
__global__ void k_head2(const float* __restrict__ w2, const float* __restrict__ b2,
                        float* __restrict__ out) {
    int c = threadIdx.x;
    int r = blockIdx.x * blockDim.y + threadIdx.y;
    if (r >= NN || c >= 28) return;
    const float* tr = g_t + (size_t)r * HH;
    float acc = 0.f;
    #pragma unroll 8
    for (int k = 0; k < HH; k++) acc = fmaf(tr[k], __ldg(&w2[k * 28 + c]), acc);
    out[(size_t)r * 28 + c] = acc + b2[c];
}

// ---------------------------------------------------------------------------
extern "C" void kernel_launch(void* const* d_in, const int* in_sizes, int n_in,
                              void* d_out, int out_size) {
    const int*   x     = (const int*)  d_in[0];
    const int*   ei    = (const int*)  d_in[1];
    const int*   ea    = (const int*)  d_in[2];
    const int*   batch = (const int*)  d_in[3];
    const float* aemb  = (const float*)d_in[4];
    const float* bemb  = (const float*)d_in[5];
    const float* vn0   = (const float*)d_in[6];
    const float* w1    = (const float*)d_in[7];
    const float* b1    = (const float*)d_in[8];
    const float* w2    = (const float*)d_in[9];
    const float* b2    = (const float*)d_in[10];
    const float* eps   = (const float*)d_in[11];
    const float* lng   = (const float*)d_in[12];
    const float* lnb   = (const float*)d_in[13];
    const float* vnw   = (const float*)d_in[14];
    const float* vnb   = (const float*)d_in[15];
    const float* vlg   = (const float*)d_in[16];
    const float* vlb   = (const float*)d_in[17];
    const float* hw1   = (const float*)d_in[18];
    const float* hb1   = (const float*)d_in[19];
    const float* hw2   = (const float*)d_in[20];
    const float* hb2   = (const float*)d_in[21];
    float* out = (float*)d_out;

    float *p_h, *p_agg, *p_t, *p_z2, *p_jk;
    cudaGetSymbolAddress((void**)&p_h,   g_h);
    cudaGetSymbolAddress((void**)&p_agg, g_agg);
    cudaGetSymbolAddress((void**)&p_t,   g_t);
    cudaGetSymbolAddress((void**)&p_z2,  g_z2);
    cudaGetSymbolAddress((void**)&p_jk,  g_jk);
    __nv_bfloat16 *w1h, *w1l, *w2h, *w2l, *hwh, *hwl;
    cudaGetSymbolAddress((void**)&w1h, g_w1t_hi);
    cudaGetSymbolAddress((void**)&w1l, g_w1t_lo);
    cudaGetSymbolAddress((void**)&w2h, g_w2t_hi);
    cudaGetSymbolAddress((void**)&w2l, g_w2t_lo);
    cudaGetSymbolAddress((void**)&hwh, g_hw1t_hi);
    cudaGetSymbolAddress((void**)&hwl, g_hw1t_lo);

    cudaFuncSetAttribute(k_gemm_bf<true, true>,   cudaFuncAttributeMaxDynamicSharedMemorySize, SMEM_TOT);
    cudaFuncSetAttribute(k_gemm_bf<false, false>, cudaFuncAttributeMaxDynamicSharedMemorySize, SMEM_TOT);
    cudaFuncSetAttribute(k_gemm_bf<false, true>,  cudaFuncAttributeMaxDynamicSharedMemorySize, SMEM_TOT);

    const int nb_nh = (NN * H4 + 255) / 256;
    dim3 ggrid(2, NNP / 128);

    // weight prep (pre-transpose + bf16 split)
    k_prep<<<(NL * HH * HH + 255) / 256, 256>>>(w1, w1h, w1l, HH, HH, NL);
    k_prep<<<(NL * HH * HH + 255) / 256, 256>>>(w2, w2h, w2l, HH, HH, NL);
    k_prep<<<(JKD * HH + 255) / 256, 256>>>(hw1, hwh, hwl, JKD, HH, 1);

    k_embed<<<nb_nh, 256>>>(x, aemb, vn0);

    for (int l = 0; l < NL; l++) {
        k_vnadd<<<nb_nh, 256>>>(batch);
        k_msg<<<(NE + 7) / 8, dim3(32, 8)>>>(ei, ea, bemb);
        k_gemm_bf<true, true><<<ggrid, 256, SMEM_TOT>>>(
            p_h, p_agg, eps, l,
            w1h + (size_t)l * HH * HH, w1l + (size_t)l * HH * HH,
            b1 + l * HH, p_t, HH);
        k_gemm_bf<false, false><<<ggrid, 256, SMEM_TOT>>>(
            p_t, nullptr, eps, l,
            w2h + (size_t)l * HH * HH, w2l + (size_t)l * HH * HH,
            b2 + l * HH, p_z2, HH);
        k_lnres<<<(NN + 7) / 8, 256>>>(batch, lng + l * HH, lnb + l * HH, l);
        k_vn<<<NG, 256>>>(vnw + (size_t)l * HH * HH, vnb + l * HH,
                          vlg + l * HH, vlb + l * HH);
    }

    k_gemm_bf<false, true><<<ggrid, 256, SMEM_TOT>>>(
        p_jk, nullptr, eps, 0, hwh, hwl, hb1, p_t, JKD);
    k_head2<<<(NN + 7) / 8, dim3(32, 8)>>>(hw2, hb2, out);
}

// round 5
// speedup vs baseline: 2.0563x; 1.1247x over previous
#include <cuda_runtime.h>
#include <cuda_bf16.h>
#include <cstdint>

#define NN  150000     // nodes
#define NNP 150016     // padded to 1172*128
#define NE  450000     // edges
#define NG  5000       // graphs
#define HH  256        // hidden
#define H4  64         // HH/4
#define JKD 1536       // (L+1)*H
#define NL  5
#define NBLK 147       // ceil(NN/1024) scan blocks

// ---------------- scratch (device globals; zero-initialized) ---------------
__device__ float g_agg  [NNP * HH];
__device__ float g_t    [NNP * HH];
__device__ float g_z2   [NNP * HH];
__device__ float g_jk   [NNP * JKD];
__device__ float g_vn   [NG * HH];
__device__ float g_vnagg[NG * HH];
// CSR (rebuilt every launch)
__device__ int g_deg [NN];
__device__ int g_off [NN + 1];
__device__ int g_cur [NN];
__device__ int g_esrc[NE];
__device__ int g_emet[NE];
__device__ int g_bsum[256];
// pre-transposed + bf16-split weights: layout [N=256 rows, K cols]
__device__ __nv_bfloat16 g_w1t_hi[NL * HH * HH];
__device__ __nv_bfloat16 g_w1t_lo[NL * HH * HH];
__device__ __nv_bfloat16 g_w2t_hi[NL * HH * HH];
__device__ __nv_bfloat16 g_w2t_lo[NL * HH * HH];
__device__ __nv_bfloat16 g_hw1t_hi[HH * JKD];
__device__ __nv_bfloat16 g_hw1t_lo[HH * JKD];

static __device__ __forceinline__ float4 f4zero() { return make_float4(0.f,0.f,0.f,0.f); }

static __device__ __forceinline__ uint32_t smem_u32(const void* p) {
    uint32_t a;
    asm("{ .reg .u64 t; cvta.to.shared.u64 t, %1; cvt.u32.u64 %0, t; }" : "=r"(a) : "l"(p));
    return a;
}
static __device__ __forceinline__ uint32_t pack_bf(float lo, float hi) {
    uint32_t d;
    asm("cvt.rn.bf16x2.f32 %0, %1, %2;" : "=r"(d) : "f"(hi), "f"(lo));
    return d;
}
static __device__ __forceinline__ void redv4(float* p, float a, float b, float c, float d) {
    asm volatile("red.global.add.v4.f32 [%0], {%1,%2,%3,%4};"
                 :: "l"(p), "f"(a), "f"(b), "f"(c), "f"(d) : "memory");
}
static __device__ __forceinline__ void ldmx4(uint32_t r[4], uint32_t addr) {
    asm volatile("ldmatrix.sync.aligned.m8n8.x4.shared.b16 {%0,%1,%2,%3}, [%4];"
                 : "=r"(r[0]), "=r"(r[1]), "=r"(r[2]), "=r"(r[3]) : "r"(addr));
}
static __device__ __forceinline__ void mma_bf(float c[4], const uint32_t a[4],
                                              uint32_t b0, uint32_t b1) {
    asm volatile("mma.sync.aligned.m16n8k16.row.col.f32.bf16.bf16.f32 "
                 "{%0,%1,%2,%3},{%4,%5,%6,%7},{%8,%9},{%0,%1,%2,%3};"
                 : "+f"(c[0]), "+f"(c[1]), "+f"(c[2]), "+f"(c[3])
                 : "r"(a[0]), "r"(a[1]), "r"(a[2]), "r"(a[3]), "r"(b0), "r"(b1));
}
static __device__ __forceinline__ void cpasync16(uint32_t dst, const void* src) {
    asm volatile("cp.async.cg.shared.global [%0], [%1], 16;" :: "r"(dst), "l"(src));
}

// ---------------- weight prep: W[K,N] -> WT_hi/lo[N,K] bf16 split -----------
__global__ void k_prep(const float* __restrict__ src, __nv_bfloat16* __restrict__ dhi,
                       __nv_bfloat16* __restrict__ dlo, int K, int N, int nmat) {
    int e = blockIdx.x * blockDim.x + threadIdx.x;
    if (e >= nmat * K * N) return;
    int m = e / (K * N), rem = e % (K * N);
    int n = rem / K, k = rem % K;
    float v = src[(size_t)m * K * N + (size_t)k * N + n];
    __nv_bfloat16 h = __float2bfloat16(v);
    __nv_bfloat16 l = __float2bfloat16(v - __bfloat162float(h));
    size_t o = (size_t)m * K * N + (size_t)n * K + k;
    dhi[o] = h; dlo[o] = l;
}

// ---------------- embed: jk[:,0:256] = atom_emb[x]; vn init; deg zero -------
__global__ void k_embed(const int* __restrict__ x,
                        const float* __restrict__ atom_emb,
                        const float* __restrict__ vn0) {
    int i = blockIdx.x * blockDim.x + threadIdx.x;
    if (i < NG * H4) {
        ((float4*)g_vnagg)[i] = f4zero();
        ((float4*)g_vn)[i] = ((const float4*)vn0)[i & (H4 - 1)];
    }
    if (i < NN) g_deg[i] = 0;
    if (i >= NN * H4) return;
    int n = i >> 6, c4 = i & 63;
    float4 v = ((const float4*)atom_emb)[x[n] * H4 + c4];
    ((float4*)g_jk)[(size_t)n * (JKD / 4) + c4] = v;
}

// ---------------- CSR build -------------------------------------------------
__global__ void k_hist(const int* __restrict__ ei) {
    int e = blockIdx.x * blockDim.x + threadIdx.x;
    if (e < NE) atomicAdd(&g_deg[ei[NE + e]], 1);
}
__global__ void k_scan1() {
    __shared__ int wsum[8];
    int b = blockIdx.x, tid = threadIdx.x;
    int lane = tid & 31, w = tid >> 5;
    int idx = b * 1024 + tid * 4;
    int4 v = make_int4(0, 0, 0, 0);
    if (idx + 3 < NN) v = *(const int4*)(g_deg + idx);
    else {
        if (idx + 0 < NN) v.x = g_deg[idx];
        if (idx + 1 < NN) v.y = g_deg[idx + 1];
        if (idx + 2 < NN) v.z = g_deg[idx + 2];
        if (idx + 3 < NN) v.w = g_deg[idx + 3];
    }
    int s = v.x + v.y + v.z + v.w;
    int t = s;
    #pragma unroll
    for (int o = 1; o < 32; o <<= 1) {
        int u = __shfl_up_sync(0xffffffffu, t, o);
        if (lane >= o) t += u;
    }
    if (lane == 31) wsum[w] = t;
    __syncthreads();
    if (w == 0 && lane < 8) {
        int u = wsum[lane];
        #pragma unroll
        for (int o = 1; o < 8; o <<= 1) {
            int x2 = __shfl_up_sync(0xffu, u, o);
            if (lane >= o) u += x2;
        }
        wsum[lane] = u;
    }
    __syncthreads();
    int excl = t - s + (w > 0 ? wsum[w - 1] : 0);
    if (idx     < NN) g_off[idx]     = excl;
    if (idx + 1 < NN) g_off[idx + 1] = excl + v.x;
    if (idx + 2 < NN) g_off[idx + 2] = excl + v.x + v.y;
    if (idx + 3 < NN) g_off[idx + 3] = excl + v.x + v.y + v.z;
    if (tid == 255) g_bsum[b] = excl + s;
}
__global__ void k_scan2() {
    __shared__ int wsum[8];
    int tid = threadIdx.x, lane = tid & 31, w = tid >> 5;
    int v = (tid < NBLK) ? g_bsum[tid] : 0;
    int t = v;
    #pragma unroll
    for (int o = 1; o < 32; o <<= 1) {
        int u = __shfl_up_sync(0xffffffffu, t, o);
        if (lane >= o) t += u;
    }
    if (lane == 31) wsum[w] = t;
    __syncthreads();
    if (w == 0 && lane < 8) {
        int u = wsum[lane];
        #pragma unroll
        for (int o = 1; o < 8; o <<= 1) {
            int x2 = __shfl_up_sync(0xffu, u, o);
            if (lane >= o) u += x2;
        }
        wsum[lane] = u;
    }
    __syncthreads();
    int excl = t - v + (w > 0 ? wsum[w - 1] : 0);
    if (tid < NBLK) g_bsum[tid] = excl;
}
__global__ void k_scan3() {
    int add = g_bsum[blockIdx.x];
    int idx = blockIdx.x * 1024 + threadIdx.x * 4;
    #pragma unroll
    for (int j = 0; j < 4; j++) {
        if (idx + j < NN) {
            int o = g_off[idx + j] + add;
            g_off[idx + j] = o;
            g_cur[idx + j] = o;
        }
    }
    if (blockIdx.x == 0 && threadIdx.x == 0) g_off[NN] = NE;
}
__global__ void k_fill(const int* __restrict__ ei, const int* __restrict__ ea,
                       const int* __restrict__ batch) {
    int e = blockIdx.x * blockDim.x + threadIdx.x;
    if (e >= NE) return;
    int src = ei[e], dst = ei[NE + e];
    int pos = atomicAdd(&g_cur[dst], 1);
    g_esrc[pos] = src;
    g_emet[pos] = ea[e] | (batch[src] << 2);
}

// ------- gather aggregation: agg[i] = sum relu(h[src]+vn[b[src]]+bond) ------
__global__ void __launch_bounds__(256)
k_agg(const float* __restrict__ bond, int l) {
    int warp = threadIdx.x >> 5, lane = threadIdx.x & 31;
    int node = blockIdx.x * 8 + warp;
    if (node >= NN) return;
    int beg = g_off[node], end = g_off[node + 1];
    float4 a0 = f4zero(), a1 = f4zero();
    const float* hb = g_jk + (size_t)l * HH + lane * 8;
    const float* vb = g_vn + lane * 8;
    const float* bb = bond + lane * 8;
    for (int base = beg; base < end; base += 32) {
        int n = end - base; if (n > 32) n = 32;
        int s = 0, m = 0;
        if (lane < n) { s = g_esrc[base + lane]; m = g_emet[base + lane]; }
        for (int j = 0; j < n; j++) {
            int src = __shfl_sync(0xffffffffu, s, j);
            int mt  = __shfl_sync(0xffffffffu, m, j);
            const float* hp = hb + (size_t)src * JKD;
            const float* vp = vb + (mt >> 2) * HH;
            const float* bp = bb + (mt & 3) * HH;
            float4 h0 = *(const float4*)hp,       h1 = *(const float4*)(hp + 4);
            float4 v0 = *(const float4*)vp,       v1 = *(const float4*)(vp + 4);
            float4 e0 = *(const float4*)bp,       e1 = *(const float4*)(bp + 4);
            a0.x += fmaxf(h0.x + v0.x + e0.x, 0.f);
            a0.y += fmaxf(h0.y + v0.y + e0.y, 0.f);
            a0.z += fmaxf(h0.z + v0.z + e0.z, 0.f);
            a0.w += fmaxf(h0.w + v0.w + e0.w, 0.f);
            a1.x += fmaxf(h1.x + v1.x + e1.x, 0.f);
            a1.y += fmaxf(h1.y + v1.y + e1.y, 0.f);
            a1.z += fmaxf(h1.z + v1.z + e1.z, 0.f);
            a1.w += fmaxf(h1.w + v1.w + e1.w, 0.f);
        }
    }
    float* ap = g_agg + (size_t)node * HH + lane * 8;
    *(float4*)ap       = a0;
    *(float4*)(ap + 4) = a1;
}

// ======= bf16-split mma.sync GEMM: C[M,256] = op(A)[M,K] @ WT^T + bias ======
// FUSEA: A_eff = (1+eps)*(A + vn[batch[row]]) + A2.
#define ROWB   80
#define TILE_B (128 * ROWB)
#define STG_B  (4 * TILE_B)
#define SMEM_TOT (2 * STG_B)

template <bool FUSEA, bool DO_RELU>
__global__ void __launch_bounds__(256, 2)
k_gemm_bf(const float* __restrict__ A, int lda, const float* __restrict__ A2,
          const int* __restrict__ batch, const float* __restrict__ vn,
          const float* __restrict__ eps, int layer,
          const __nv_bfloat16* __restrict__ Bh, const __nv_bfloat16* __restrict__ Bl,
          const float* __restrict__ bias, float* __restrict__ C, int K) {
    extern __shared__ __align__(128) char smem[];
    const int tid = threadIdx.x, warp = tid >> 5, lane = tid & 31;
    const int brow = blockIdx.y * 128, bcol = blockIdx.x * 128;
    const int wm = warp & 3, wn = warp >> 2;
    const int nch = K >> 5;

    float alpha = 1.f;
    if (FUSEA) alpha = 1.f + __ldg(&eps[layer]);

    const int ar = tid >> 1, ahf = tid & 1;
    const int arow = brow + ar;
    const float* Ap  = A + (size_t)arow * lda + ahf * 16;
    const float* A2p = FUSEA ? (A2 + (size_t)arow * HH + ahf * 16) : nullptr;
    const float* Vp  = nullptr;
    if (FUSEA) {
        int bidx = (arow < NN) ? __ldg(&batch[arow]) : 0;
        Vp = vn + (size_t)bidx * HH + ahf * 16;
    }
    const int bro = tid & 127;
    const __nv_bfloat16* Bp = ((tid >> 7) ? Bl : Bh) + (size_t)(bcol + bro) * K;

    const uint32_t sb = smem_u32(smem);

    auto issue = [&](int c, int s) {
        char* st = smem + s * STG_B;
        uint32_t bdst = sb + s * STG_B + (2 + (tid >> 7)) * TILE_B + bro * ROWB;
        const char* bsrc = (const char*)(Bp + c * 32);
        #pragma unroll
        for (int j = 0; j < 4; j++) cpasync16(bdst + j * 16, bsrc + j * 16);
        const float* ap = Ap + c * 32;
        float f[16];
        #pragma unroll
        for (int j = 0; j < 4; j++) *(float4*)(f + 4 * j) = *(const float4*)(ap + 4 * j);
        if (FUSEA) {
            const float* a2p = A2p + c * 32;
            const float* vp  = Vp + c * 32;
            #pragma unroll
            for (int j = 0; j < 4; j++) {
                float4 u = *(const float4*)(a2p + 4 * j);
                float4 v = *(const float4*)(vp + 4 * j);
                f[4*j+0] = fmaf(alpha, f[4*j+0] + v.x, u.x);
                f[4*j+1] = fmaf(alpha, f[4*j+1] + v.y, u.y);
                f[4*j+2] = fmaf(alpha, f[4*j+2] + v.z, u.z);
                f[4*j+3] = fmaf(alpha, f[4*j+3] + v.w, u.w);
            }
        }
        uint32_t hi[8], lo[8];
        #pragma unroll
        for (int q = 0; q < 8; q++) {
            float f0 = f[2*q], f1 = f[2*q+1];
            __nv_bfloat16 h0 = __float2bfloat16(f0), h1 = __float2bfloat16(f1);
            hi[q] = ((uint32_t)__bfloat16_as_ushort(h1) << 16) | __bfloat16_as_ushort(h0);
            lo[q] = pack_bf(f0 - __bfloat162float(h0), f1 - __bfloat162float(h1));
        }
        char* arow_p = st + ar * ROWB + ahf * 32;
        *(uint4*)(arow_p)               = make_uint4(hi[0], hi[1], hi[2], hi[3]);
        *(uint4*)(arow_p + 16)          = make_uint4(hi[4], hi[5], hi[6], hi[7]);
        *(uint4*)(arow_p + TILE_B)      = make_uint4(lo[0], lo[1], lo[2], lo[3]);
        *(uint4*)(arow_p + TILE_B + 16) = make_uint4(lo[4], lo[5], lo[6], lo[7]);
        asm volatile("cp.async.commit_group;" ::: "memory");
    };

    float acc[2][8][4];
    #pragma unroll
    for (int mi = 0; mi < 2; mi++)
        #pragma unroll
        for (int ni = 0; ni < 8; ni++)
            #pragma unroll
            for (int j = 0; j < 4; j++) acc[mi][ni][j] = 0.f;

    const uint32_t a_addr = sb + (uint32_t)(wm * 32 + (lane & 15)) * ROWB + (lane >> 4) * 16;
    const int bn = wn * 64 + (lane & 7) + ((lane >> 4) << 3);
    const uint32_t b_addr = sb + 2 * TILE_B + (uint32_t)bn * ROWB + ((lane >> 3) & 1) * 16;

    issue(0, 0);
    for (int c = 0; c < nch; c++) {
        const int s = c & 1;
        if (c + 1 < nch) {
            issue(c + 1, 1 - s);
            asm volatile("cp.async.wait_group 1;" ::: "memory");
        } else {
            asm volatile("cp.async.wait_group 0;" ::: "memory");
        }
        __syncthreads();
        const uint32_t so = s * STG_B;
        #pragma unroll
        for (int k16 = 0; k16 < 2; k16++) {
            uint32_t ah[2][4], al[2][4];
            #pragma unroll
            for (int mi = 0; mi < 2; mi++) {
                uint32_t aa = a_addr + so + mi * (16 * ROWB) + k16 * 32;
                ldmx4(ah[mi], aa);
                ldmx4(al[mi], aa + TILE_B);
            }
            #pragma unroll
            for (int np = 0; np < 4; np++) {
                uint32_t ba = b_addr + so + np * (16 * ROWB) + k16 * 32;
                uint32_t bh[4], bl[4];
                ldmx4(bh, ba);
                ldmx4(bl, ba + TILE_B);
                #pragma unroll
                for (int g = 0; g < 2; g++) {
                    #pragma unroll
                    for (int mi = 0; mi < 2; mi++) {
                        float* cc = acc[mi][np * 2 + g];
                        mma_bf(cc, ah[mi], bh[2*g], bh[2*g+1]);
                        mma_bf(cc, ah[mi], bl[2*g], bl[2*g+1]);
                        mma_bf(cc, al[mi], bh[2*g], bh[2*g+1]);
                    }
                }
            }
        }
        __syncthreads();
    }

    #pragma unroll
    for (int mi = 0; mi < 2; mi++) {
        int r0 = brow + wm * 32 + mi * 16 + (lane >> 2);
        #pragma unroll
        for (int ni = 0; ni < 8; ni++) {
            int col = bcol + wn * 64 + ni * 8 + (lane & 3) * 2;
            float b0 = __ldg(&bias[col]), b1 = __ldg(&bias[col + 1]);
            float v0 = acc[mi][ni][0] + b0, v1 = acc[mi][ni][1] + b1;
            float v2 = acc[mi][ni][2] + b0, v3 = acc[mi][ni][3] + b1;
            if (DO_RELU) {
                v0 = fmaxf(v0, 0.f); v1 = fmaxf(v1, 0.f);
                v2 = fmaxf(v2, 0.f); v3 = fmaxf(v3, 0.f);
            }
            *(float2*)(C + (size_t)r0 * 256 + col)       = make_float2(v0, v1);
            *(float2*)(C + (size_t)(r0 + 8) * 256 + col) = make_float2(v2, v3);
        }
    }
}

// ------- LN + relu + residual(h_old+vnb); write jk slice; vn segment-sum ----
__global__ void __launch_bounds__(256)
k_lnres(const int* __restrict__ batch, const float* __restrict__ lng,
        const float* __restrict__ lnb, int layer) {
    int w = threadIdx.x >> 5, lane = threadIdx.x & 31;
    int r = blockIdx.x * 8 + w;
    if (r >= NN) return;
    const float4* z4 = (const float4*)(g_z2 + (size_t)r * HH);
    float4 a = z4[lane * 2], b = z4[lane * 2 + 1];
    float s  = a.x + a.y + a.z + a.w + b.x + b.y + b.z + b.w;
    float ss = a.x*a.x + a.y*a.y + a.z*a.z + a.w*a.w
             + b.x*b.x + b.y*b.y + b.z*b.z + b.w*b.w;
    #pragma unroll
    for (int o = 16; o; o >>= 1) {
        s  += __shfl_xor_sync(0xffffffffu, s,  o);
        ss += __shfl_xor_sync(0xffffffffu, ss, o);
    }
    float mean = s * (1.f / HH);
    float var  = ss * (1.f / HH) - mean * mean;
    float rstd = rsqrtf(var + 1e-5f);

    float4 g0 = ((const float4*)lng)[lane * 2], g1 = ((const float4*)lng)[lane * 2 + 1];
    float4 b0 = ((const float4*)lnb)[lane * 2], b1 = ((const float4*)lnb)[lane * 2 + 1];
    const float4* hv = (const float4*)(g_jk + (size_t)r * JKD + layer * HH);
    const float4* vv = (const float4*)(g_vn + (size_t)__ldg(&batch[r]) * HH);
    float4 h0 = hv[lane * 2], h1 = hv[lane * 2 + 1];
    float4 w0 = vv[lane * 2], w1 = vv[lane * 2 + 1];

    float4 o0, o1;
    o0.x = fmaxf((a.x - mean) * rstd * g0.x + b0.x, 0.f) + h0.x + w0.x;
    o0.y = fmaxf((a.y - mean) * rstd * g0.y + b0.y, 0.f) + h0.y + w0.y;
    o0.z = fmaxf((a.z - mean) * rstd * g0.z + b0.z, 0.f) + h0.z + w0.z;
    o0.w = fmaxf((a.w - mean) * rstd * g0.w + b0.w, 0.f) + h0.w + w0.w;
    o1.x = fmaxf((b.x - mean) * rstd * g1.x + b1.x, 0.f) + h1.x + w1.x;
    o1.y = fmaxf((b.y - mean) * rstd * g1.y + b1.y, 0.f) + h1.y + w1.y;
    o1.z = fmaxf((b.z - mean) * rstd * g1.z + b1.z, 0.f) + h1.z + w1.z;
    o1.w = fmaxf((b.w - mean) * rstd * g1.w + b1.w, 0.f) + h1.w + w1.w;

    float4* jkp = (float4*)(g_jk + (size_t)r * JKD + (layer + 1) * HH);
    jkp[lane * 2]     = o0;
    jkp[lane * 2 + 1] = o1;
    float* va = g_vnagg + (size_t)__ldg(&batch[r]) * HH + lane * 8;
    redv4(va,     o0.x, o0.y, o0.z, o0.w);
    redv4(va + 4, o1.x, o1.y, o1.z, o1.w);
}

// ------- virtual node: vn = relu(LN((vnagg+vn) @ W + b)); reset vnagg -------
__global__ void __launch_bounds__(256)
k_vn(const float* __restrict__ w, const float* __restrict__ bias,
     const float* __restrict__ lng, const float* __restrict__ lnb) {
    int g = blockIdx.x, t = threadIdx.x;
    __shared__ float s[HH];
    __shared__ float red[2][8];
    float sv = g_vnagg[(size_t)g * HH + t] + g_vn[(size_t)g * HH + t];
    s[t] = sv;
    g_vnagg[(size_t)g * HH + t] = 0.f;
    __syncthreads();
    float acc = bias[t];
    #pragma unroll 8
    for (int k = 0; k < HH; k++) acc = fmaf(s[k], w[k * HH + t], acc);
    float sm = acc, sq = acc * acc;
    int lane = t & 31, wid = t >> 5;
    #pragma unroll
    for (int o = 16; o; o >>= 1) {
        sm += __shfl_xor_sync(0xffffffffu, sm, o);
        sq += __shfl_xor_sync(0xffffffffu, sq, o);
    }
    if (lane == 0) { red[0][wid] = sm; red[1][wid] = sq; }
    __syncthreads();
    float tot = 0.f, tot2 = 0.f;
    #pragma unroll
    for (int i = 0; i < 8; i++) { tot += red[0][i]; tot2 += red[1][i]; }
    float mean = tot * (1.f / HH);
    float var  = tot2 * (1.f / HH) - mean * mean;
    float rstd = rsqrtf(var + 1e-5f);
    float y = (acc - mean) * rstd * lng[t] + lnb[t];
    g_vn[(size_t)g * HH + t] = fmaxf(y, 0.f);
}

// ------- head stage 2: out[N,28] = t[N,256] @ w2[256,28] + b2 ---------------
__global__ void k_head2(const float* __restrict__ w2, const float* __restrict__ b2,
                        float* __restrict__ out) {
    int c = threadIdx.x;
    int r = blockIdx.x * blockDim.y + threadIdx.y;
    if (r >= NN || c >= 28) return;
    const float* tr = g_t + (size_t)r * HH;
    float acc = 0.f;
    #pragma unroll 8
    for (int k = 0; k < HH; k++) acc = fmaf(tr[k], __ldg(&w2[k * 28 + c]), acc);
    out[(size_t)r * 28 + c] = acc + b2[c];
}

// ---------------------------------------------------------------------------
extern "C" void kernel_launch(void* const* d_in, const int* in_sizes, int n_in,
                              void* d_out, int out_size) {
    const int*   x     = (const int*)  d_in[0];
    const int*   ei    = (const int*)  d_in[1];
    const int*   ea    = (const int*)  d_in[2];
    const int*   batch = (const int*)  d_in[3];
    const float* aemb  = (const float*)d_in[4];
    const float* bemb  = (const float*)d_in[5];
    const float* vn0   = (const float*)d_in[6];
    const float* w1    = (const float*)d_in[7];
    const float* b1    = (const float*)d_in[8];
    const float* w2    = (const float*)d_in[9];
    const float* b2    = (const float*)d_in[10];
    const float* eps   = (const float*)d_in[11];
    const float* lng   = (const float*)d_in[12];
    const float* lnb   = (const float*)d_in[13];
    const float* vnw   = (const float*)d_in[14];
    const float* vnb   = (const float*)d_in[15];
    const float* vlg   = (const float*)d_in[16];
    const float* vlb   = (const float*)d_in[17];
    const float* hw1   = (const float*)d_in[18];
    const float* hb1   = (const float*)d_in[19];
    const float* hw2   = (const float*)d_in[20];
    const float* hb2   = (const float*)d_in[21];
    float* out = (float*)d_out;

    float *p_agg, *p_t, *p_z2, *p_jk, *p_vn;
    cudaGetSymbolAddress((void**)&p_agg, g_agg);
    cudaGetSymbolAddress((void**)&p_t,   g_t);
    cudaGetSymbolAddress((void**)&p_z2,  g_z2);
    cudaGetSymbolAddress((void**)&p_jk,  g_jk);
    cudaGetSymbolAddress((void**)&p_vn,  g_vn);
    __nv_bfloat16 *w1h, *w1l, *w2h, *w2l, *hwh, *hwl;
    cudaGetSymbolAddress((void**)&w1h, g_w1t_hi);
    cudaGetSymbolAddress((void**)&w1l, g_w1t_lo);
    cudaGetSymbolAddress((void**)&w2h, g_w2t_hi);
    cudaGetSymbolAddress((void**)&w2l, g_w2t_lo);
    cudaGetSymbolAddress((void**)&hwh, g_hw1t_hi);
    cudaGetSymbolAddress((void**)&hwl, g_hw1t_lo);

    cudaFuncSetAttribute(k_gemm_bf<true, true>,   cudaFuncAttributeMaxDynamicSharedMemorySize, SMEM_TOT);
    cudaFuncSetAttribute(k_gemm_bf<false, false>, cudaFuncAttributeMaxDynamicSharedMemorySize, SMEM_TOT);
    cudaFuncSetAttribute(k_gemm_bf<false, true>,  cudaFuncAttributeMaxDynamicSharedMemorySize, SMEM_TOT);

    const int nb_nh = (NN * H4 + 255) / 256;
    dim3 ggrid(2, NNP / 128);

    // weight prep
    k_prep<<<(NL * HH * HH + 255) / 256, 256>>>(w1, w1h, w1l, HH, HH, NL);
    k_prep<<<(NL * HH * HH + 255) / 256, 256>>>(w2, w2h, w2l, HH, HH, NL);
    k_prep<<<(JKD * HH + 255) / 256, 256>>>(hw1, hwh, hwl, JKD, HH, 1);

    // embed (+deg zero) then CSR build
    k_embed<<<nb_nh, 256>>>(x, aemb, vn0);
    k_hist<<<(NE + 255) / 256, 256>>>(ei);
    k_scan1<<<NBLK, 256>>>();
    k_scan2<<<1, 256>>>();
    k_scan3<<<NBLK, 256>>>();
    k_fill<<<(NE + 255) / 256, 256>>>(ei, ea, batch);

    for (int l = 0; l < NL; l++) {
        k_agg<<<(NN + 7) / 8, 256>>>(bemb, l);
        // t = relu(((1+eps)*(h+vnb) + agg) @ w1 + b1)
        k_gemm_bf<true, true><<<ggrid, 256, SMEM_TOT>>>(
            p_jk + (size_t)l * HH, JKD, p_agg, batch, p_vn, eps, l,
            w1h + (size_t)l * HH * HH, w1l + (size_t)l * HH * HH,
            b1 + l * HH, p_t, HH);
        // z2 = t @ w2 + b2
        k_gemm_bf<false, false><<<ggrid, 256, SMEM_TOT>>>(
            p_t, HH, nullptr, nullptr, nullptr, eps, l,
            w2h + (size_t)l * HH * HH, w2l + (size_t)l * HH * HH,
            b2 + l * HH, p_z2, HH);
        k_lnres<<<(NN + 7) / 8, 256>>>(batch, lng + l * HH, lnb + l * HH, l);
        k_vn<<<NG, 256>>>(vnw + (size_t)l * HH * HH, vnb + l * HH,
                          vlg + l * HH, vlb + l * HH);
    }

    // head
    k_gemm_bf<false, true><<<ggrid, 256, SMEM_TOT>>>(
        p_jk, JKD, nullptr, nullptr, nullptr, eps, 0, hwh, hwl, hb1, p_t, JKD);
    k_head2<<<(NN + 7) / 8, dim3(32, 8)>>>(hw2, hb2, out);
}